// round 1
// baseline (speedup 1.0000x reference)
#include <cuda_runtime.h>

// Fused: conv(dna)+relu, conv(prot)+relu, batch-mixing chunk shuffle,
// 32x32x3 attention (q=prot, k=v=dna), 96->2 linear.
//
// Shuffle algebra: sd[b',q,c] = d[32*(b'&1023)+q, 3*(b'>>10)+c]  (B=2^15).
// CTA r owns source rows 32r..32r+31 and output batches b' = r + 1024n, n=0..31.

#define CLEN 103      // per-channel input length
#define NOUT 96       // conv output length
#define CH_DNA 4
#define CH_PROT 21
#define RLEN_DNA (CH_DNA * CLEN)    // 412
#define RLEN_PROT (CH_PROT * CLEN)  // 2163
#define XS_STRIDE 105 // staged row stride (mod 4 == 1 -> conflict-free reads)
#define DS_STRIDE 97  // conv-output row stride (mod 32 == 1 -> conflict-free)

__shared__ float xs_sm[8][4 * XS_STRIDE];   // per-warp channel staging (4 rows x 103)
__shared__ float d_sm[32 * DS_STRIDE];      // relu(conv(dna)) 32 rows x 96
__shared__ float p_sm[32 * DS_STRIDE];      // relu(conv(prot))
__shared__ float wp_sm[CH_PROT * 8];
__shared__ float wd_sm[CH_DNA * 8];
__shared__ float wl_sm[2 * 96];
__shared__ float bl_sm[2];

// Conv for 4 rows handled by one warp. Lane (g = lane>>3, s = lane&7):
// row-in-group g, output block t in [12s, 12s+12).
template <int C>
__device__ __forceinline__ void conv_rows(
    const float* __restrict__ base,   // &src[(32r + 4w) * rlen]
    int rlen,
    const float* __restrict__ wsm,    // [C][8] weights in smem
    float* __restrict__ outsm,        // d_sm or p_sm
    float* __restrict__ xw,           // this warp's staging buffer
    int lane, int g, int s, int rowl) // rowl = 4w + g
{
    float acc[12];
#pragma unroll
    for (int t = 0; t < 12; t++) acc[t] = 0.f;

    // prefetch channel 0: 4 rows x 103 floats, coalesced
    float cur[13];
#pragma unroll
    for (int kk = 0; kk < 13; kk++) {
        int i = lane + kk * 32;
        float v = 0.f;
        if (i < 4 * CLEN) {
            int row = i / CLEN;
            int posc = i - row * CLEN;
            v = base[(size_t)row * rlen + posc];
        }
        cur[kk] = v;
    }

    for (int c = 0; c < C; c++) {
        // commit staged channel c to smem
#pragma unroll
        for (int kk = 0; kk < 13; kk++) {
            int i = lane + kk * 32;
            if (i < 4 * CLEN) {
                int row = i / CLEN;
                int posc = i - row * CLEN;
                xw[row * XS_STRIDE + posc] = cur[kk];
            }
        }
        __syncwarp();

        // prefetch channel c+1 (LDG latency overlaps the FMA block below)
        if (c + 1 < C) {
            const float* cb = base + (c + 1) * CLEN;
#pragma unroll
            for (int kk = 0; kk < 13; kk++) {
                int i = lane + kk * 32;
                float v = 0.f;
                if (i < 4 * CLEN) {
                    int row = i / CLEN;
                    int posc = i - row * CLEN;
                    v = cb[(size_t)row * rlen + posc];
                }
                cur[kk] = v;
            }
        }

        float wj[8];
#pragma unroll
        for (int j = 0; j < 8; j++) wj[j] = wsm[c * 8 + j];

        float x[19];
        const float* xrow = &xw[g * XS_STRIDE + 12 * s];
#pragma unroll
        for (int u = 0; u < 19; u++) x[u] = xrow[u];

#pragma unroll
        for (int t = 0; t < 12; t++) {
#pragma unroll
            for (int j = 0; j < 8; j++) {
                acc[t] = fmaf(x[t + j], wj[j], acc[t]);
            }
        }
        __syncwarp();  // protect staging buffer before next channel's commit
    }

    // relu + store 12 outputs
#pragma unroll
    for (int t = 0; t < 12; t++) {
        outsm[rowl * DS_STRIDE + 12 * s + t] = fmaxf(acc[t], 0.f);
    }
}

__global__ __launch_bounds__(256)
void fused_matx_kernel(
    const float* __restrict__ dna, const float* __restrict__ prot,
    const float* __restrict__ w_dna, const float* __restrict__ w_prot,
    const float* __restrict__ w_lin, const float* __restrict__ b_lin,
    float* __restrict__ out)
{
    const int tid = threadIdx.x;
    const int w = tid >> 5;
    const int lane = tid & 31;
    const int g = lane >> 3;
    const int s = lane & 7;
    const int r = blockIdx.x;      // 0..1023

    // load weights to smem
    if (tid < CH_PROT * 8) wp_sm[tid] = w_prot[tid];
    if (tid < CH_DNA * 8)  wd_sm[tid] = w_dna[tid];
    if (tid >= 32 && tid < 32 + 192) wl_sm[tid - 32] = w_lin[tid - 32];
    if (tid == 255) { bl_sm[0] = b_lin[0]; bl_sm[1] = b_lin[1]; }
    __syncthreads();

    const int rowl = 4 * w + g;  // local source row this lane contributes to

    // conv(dna) -> d_sm
    {
        const float* base = dna + (size_t)(32 * r + 4 * w) * RLEN_DNA;
        conv_rows<CH_DNA>(base, RLEN_DNA, wd_sm, d_sm, xs_sm[w], lane, g, s, rowl);
    }
    // conv(prot) -> p_sm
    {
        const float* base = prot + (size_t)(32 * r + 4 * w) * RLEN_PROT;
        conv_rows<CH_PROT>(base, RLEN_PROT, wp_sm, p_sm, xs_sm[w], lane, g, s, rowl);
    }

    __syncthreads();

    // Attention + linear. Warp w handles chunk indices n = w + 8*it.
    const float b0 = bl_sm[0];
    const float b1 = bl_sm[1];
    const float scale = 0.5773502691896258f;  // 1/sqrt(3)
    const int q = lane;

#pragma unroll
    for (int it = 0; it < 4; it++) {
        const int n = w + 8 * it;
        const int col = 3 * n;

        const float sp0 = p_sm[q * DS_STRIDE + col + 0];
        const float sp1 = p_sm[q * DS_STRIDE + col + 1];
        const float sp2 = p_sm[q * DS_STRIDE + col + 2];
        const float sd0 = d_sm[q * DS_STRIDE + col + 0];
        const float sd1 = d_sm[q * DS_STRIDE + col + 1];
        const float sd2 = d_sm[q * DS_STRIDE + col + 2];

        float l[32];
#pragma unroll
        for (int k = 0; k < 32; k++) {
            float a0 = __shfl_sync(0xffffffffu, sd0, k);
            float a1 = __shfl_sync(0xffffffffu, sd1, k);
            float a2 = __shfl_sync(0xffffffffu, sd2, k);
            l[k] = (sp0 * a0 + sp1 * a1 + sp2 * a2) * scale;
        }

        float m = l[0];
#pragma unroll
        for (int k = 1; k < 32; k++) m = fmaxf(m, l[k]);

        float ssum = 0.f, o0 = 0.f, o1 = 0.f, o2 = 0.f;
#pragma unroll
        for (int k = 0; k < 32; k++) {
            float e = __expf(l[k] - m);
            ssum += e;
            float a0 = __shfl_sync(0xffffffffu, sd0, k);
            float a1 = __shfl_sync(0xffffffffu, sd1, k);
            float a2 = __shfl_sync(0xffffffffu, sd2, k);
            o0 = fmaf(e, a0, o0);
            o1 = fmaf(e, a1, o1);
            o2 = fmaf(e, a2, o2);
        }
        const float inv = 1.0f / ssum;
        o0 *= inv; o1 *= inv; o2 *= inv;

        // linear: y_j = sum_c o_c * w_lin[j, 3q+c], then warp-reduce over q
        float y0 = o0 * wl_sm[3 * q + 0] + o1 * wl_sm[3 * q + 1] + o2 * wl_sm[3 * q + 2];
        float y1 = o0 * wl_sm[96 + 3 * q + 0] + o1 * wl_sm[96 + 3 * q + 1] + o2 * wl_sm[96 + 3 * q + 2];
#pragma unroll
        for (int off = 16; off > 0; off >>= 1) {
            y0 += __shfl_xor_sync(0xffffffffu, y0, off);
            y1 += __shfl_xor_sync(0xffffffffu, y1, off);
        }

        if (lane == 0) {
            const int bp = r + 1024 * n;     // output batch
            out[2 * bp + 0] = y0 + b0;
            out[2 * bp + 1] = y1 + b1;
        }
    }
}

extern "C" void kernel_launch(void* const* d_in, const int* in_sizes, int n_in,
                              void* d_out, int out_size)
{
    (void)in_sizes; (void)n_in; (void)out_size;
    const float* dna    = (const float*)d_in[0];
    const float* prot   = (const float*)d_in[1];
    const float* w_dna  = (const float*)d_in[2];
    const float* w_prot = (const float*)d_in[3];
    const float* w_lin  = (const float*)d_in[4];
    const float* b_lin  = (const float*)d_in[5];

    fused_matx_kernel<<<1024, 256>>>(dna, prot, w_dna, w_prot, w_lin, b_lin,
                                     (float*)d_out);
}

// round 3
// speedup vs baseline: 2.0255x; 2.0255x over previous
#include <cuda_runtime.h>
#include <cstdint>

// Fused conv+relu (dna, prot) -> chunk shuffle -> 32x32x3 attention -> 96->2
// linear. v3: persistent CTAs (grid = #SMs), cp.async.bulk (UBLKCP)
// double-buffered prot chunks + pipelined dna, copies issued across r-iteration
// boundaries so the pipeline never drains.
//
// Shuffle algebra: sd[b',q,c] = d[32*(b'&1023)+q, 3*(b'>>10)+c]  (B=2^15).
// Source-row block r owns rows 32r..32r+31, output batches b' = r + 1024n.

#define NR 1024                 // number of 32-row blocks
#define CLEN 103
#define RLEN_DNA 412            // 4*103
#define RLEN_PROT 2163          // 21*103
#define DS 97                   // conv-output row stride (mod 32 == 1)
#define PB_FLOATS (8 * RLEN_PROT)            // 17304 per prot buffer
#define DNA_FLOATS (32 * RLEN_DNA)           // 13184
#define CH_BYTES (PB_FLOATS * 4)             // 69216 (16B multiple)
#define DNA_BYTES (DNA_FLOATS * 4)           // 52736 (16B multiple)

// smem layout (floats)
#define OFF_MBAR 0              // 8 x u64 = 16 floats
#define OFF_WD   16
#define OFF_WP   (OFF_WD + 32)
#define OFF_WL   (OFF_WP + 168)
#define OFF_BL   (OFF_WL + 192)
#define OFF_PB0  416            // 16B aligned
#define OFF_PB1  (OFF_PB0 + PB_FLOATS)
#define OFF_DNA  (OFF_PB0 + 2 * PB_FLOATS)
#define OFF_DSM  (OFF_DNA + DNA_FLOATS)
#define OFF_PSM  (OFF_DSM + 32 * DS)
#define SMEM_FLOATS (OFF_PSM + 32 * DS)
#define SMEM_BYTES (SMEM_FLOATS * 4)         // 217664

__device__ __forceinline__ uint32_t s2u(const void* p) {
    uint32_t a;
    asm("{ .reg .u64 t; cvta.to.shared.u64 t, %1; cvt.u32.u64 %0, t; }"
        : "=r"(a) : "l"(p));
    return a;
}
__device__ __forceinline__ void mbar_init(uint32_t mbar, uint32_t cnt) {
    asm volatile("mbarrier.init.shared.b64 [%0], %1;" :: "r"(mbar), "r"(cnt) : "memory");
}
__device__ __forceinline__ void mbar_expect_tx(uint32_t mbar, uint32_t bytes) {
    asm volatile("mbarrier.arrive.expect_tx.shared.b64 _, [%0], %1;"
                 :: "r"(mbar), "r"(bytes) : "memory");
}
// known-good acquire wait (matches ptx_helpers.cuh MBARRIER_WAIT_PARITY)
__device__ __forceinline__ void mbar_wait(uint32_t mbar, uint32_t parity) {
    uint32_t done;
    asm volatile(
        "{\n\t"
        ".reg .pred p;\n\t"
        "mbarrier.try_wait.parity.acquire.cta.shared::cta.b64 p, [%1], %2;\n\t"
        "selp.b32 %0, 1, 0, p;\n\t"
        "}"
        : "=r"(done) : "r"(mbar), "r"(parity) : "memory");
    if (!done) {
        asm volatile(
            "{\n\t"
            ".reg .pred P1;\n\t"
            "WL_%=:\n\t"
            "mbarrier.try_wait.parity.acquire.cta.shared::cta.b64 P1, [%0], %1, 0x989680;\n\t"
            "@P1 bra.uni WD_%=;\n\t"
            "bra.uni WL_%=;\n\t"
            "WD_%=:\n\t"
            "}"
            :: "r"(mbar), "r"(parity) : "memory");
    }
}
// known-good Hopper/Blackwell bulk-copy form (shared::cluster dst space)
__device__ __forceinline__ void bulk_g2s(uint32_t dst, const void* src,
                                         uint32_t bytes, uint32_t mbar) {
    asm volatile(
        "cp.async.bulk.shared::cluster.global.mbarrier::complete_tx::bytes "
        "[%0], [%1], %2, [%3];"
        :: "r"(dst), "l"(src), "r"(bytes), "r"(mbar) : "memory");
}

// One warp computes one conv row; lane computes outputs 3*lane..3*lane+2.
// smem reads stride 3 floats across lanes -> conflict-free.
template <int C>
__device__ __forceinline__ void conv_row(const float* __restrict__ xrow,
                                         const float* __restrict__ wsm,
                                         float* __restrict__ orow, int lane) {
    float a0 = 0.f, a1 = 0.f, a2 = 0.f;
#pragma unroll
    for (int c = 0; c < C; c++) {
        const float* xb = xrow + c * CLEN + 3 * lane;
        float x[10];
#pragma unroll
        for (int u = 0; u < 10; u++) x[u] = xb[u];
        const float4 w0 = *(const float4*)(wsm + c * 8);
        const float4 w1 = *(const float4*)(wsm + c * 8 + 4);
        const float wj[8] = {w0.x, w0.y, w0.z, w0.w, w1.x, w1.y, w1.z, w1.w};
#pragma unroll
        for (int jt = 0; jt < 8; jt++) {
            a0 = fmaf(x[jt + 0], wj[jt], a0);
            a1 = fmaf(x[jt + 1], wj[jt], a1);
            a2 = fmaf(x[jt + 2], wj[jt], a2);
        }
    }
    orow[3 * lane + 0] = fmaxf(a0, 0.f);
    orow[3 * lane + 1] = fmaxf(a1, 0.f);
    orow[3 * lane + 2] = fmaxf(a2, 0.f);
}

__global__ __launch_bounds__(256)
void fused_matx_v3(const float* __restrict__ dna, const float* __restrict__ prot,
                   const float* __restrict__ w_dna, const float* __restrict__ w_prot,
                   const float* __restrict__ w_lin, const float* __restrict__ b_lin,
                   float* __restrict__ out)
{
    extern __shared__ float sm[];
    uint64_t* mbars = (uint64_t*)(sm + OFF_MBAR);   // [0]=p0 [1]=p1 [2]=dna
    float* wd   = sm + OFF_WD;
    float* wp   = sm + OFF_WP;
    float* wl   = sm + OFF_WL;
    float* bl   = sm + OFF_BL;
    float* pb[2] = { sm + OFF_PB0, sm + OFF_PB1 };
    float* dna_st = sm + OFF_DNA;
    float* d_sm = sm + OFF_DSM;
    float* p_sm = sm + OFF_PSM;

    const int tid  = threadIdx.x;
    const int w    = tid >> 5;
    const int lane = tid & 31;
    const int bid  = blockIdx.x;
    const int grid = gridDim.x;

    const uint32_t mb_p[2] = { s2u(&mbars[0]), s2u(&mbars[1]) };
    const uint32_t mb_dna  = s2u(&mbars[2]);
    const uint32_t pbu[2]  = { s2u(pb[0]), s2u(pb[1]) };
    const uint32_t dnau    = s2u(dna_st);

    if (tid == 0) { mbar_init(mb_p[0], 1); mbar_init(mb_p[1], 1); mbar_init(mb_dna, 1); }
    if (tid < 32)  wd[tid] = w_dna[tid];
    if (tid < 168) wp[tid] = w_prot[tid];
    if (tid < 192) wl[tid] = w_lin[tid];
    if (tid < 2)   bl[tid] = b_lin[tid];
    __syncthreads();

    if (bid >= NR) return;

    // prologue: dna(r0), prot chunks s=0,1
    if (tid == 0) {
        mbar_expect_tx(mb_dna, DNA_BYTES);
        bulk_g2s(dnau, dna + (size_t)bid * DNA_FLOATS, DNA_BYTES, mb_dna);
        mbar_expect_tx(mb_p[0], CH_BYTES);
        bulk_g2s(pbu[0], prot + (size_t)(32 * bid + 0) * RLEN_PROT, CH_BYTES, mb_p[0]);
        mbar_expect_tx(mb_p[1], CH_BYTES);
        bulk_g2s(pbu[1], prot + (size_t)(32 * bid + 8) * RLEN_PROT, CH_BYTES, mb_p[1]);
    }

    const float b0 = bl[0], b1 = bl[1];
    const float scale = 0.5773502691896258f;  // 1/sqrt(3)

    int it = 0;
    for (int r = bid; r < NR; r += grid, it++) {
        // ── dna conv: warp w does rows w, w+8, w+16, w+24 ──
        mbar_wait(mb_dna, it & 1);
#pragma unroll
        for (int i = 0; i < 4; i++) {
            const int row = w + 8 * i;
            conv_row<4>(dna_st + row * RLEN_DNA, wd, d_sm + row * DS, lane);
        }
        __syncthreads();                       // dna_st free
        if (tid == 0 && r + grid < NR) {       // prefetch next r's dna
            mbar_expect_tx(mb_dna, DNA_BYTES);
            bulk_g2s(dnau, dna + (size_t)(r + grid) * DNA_FLOATS, DNA_BYTES, mb_dna);
        }

        // ── prot conv: global chunk stream s = 4*it + j ──
#pragma unroll
        for (int j = 0; j < 4; j++) {
            const int s = 4 * it + j;
            const int b = s & 1;
            mbar_wait(mb_p[b], (s >> 1) & 1);
            conv_row<21>(pb[b] + w * RLEN_PROT, wp, p_sm + (8 * j + w) * DS, lane);
            __syncthreads();                   // buffer b free
            // issue chunk s+2 (may belong to next r)
            const int s2 = s + 2;
            const int it2 = s2 >> 2, j2 = s2 & 3;
            const int r2 = bid + it2 * grid;
            if (tid == 0 && r2 < NR) {
                mbar_expect_tx(mb_p[s2 & 1], CH_BYTES);
                bulk_g2s(pbu[s2 & 1],
                         prot + (size_t)(32 * r2 + 8 * j2) * RLEN_PROT,
                         CH_BYTES, mb_p[s2 & 1]);
            }
        }

        // ── attention + linear: warp w handles chunks n = w + 8*itc ──
        const int q = lane;
#pragma unroll
        for (int itc = 0; itc < 4; itc++) {
            const int n = w + 8 * itc;
            const int col = 3 * n;

            const float sp0 = p_sm[q * DS + col + 0];
            const float sp1 = p_sm[q * DS + col + 1];
            const float sp2 = p_sm[q * DS + col + 2];
            const float sd0 = d_sm[q * DS + col + 0];
            const float sd1 = d_sm[q * DS + col + 1];
            const float sd2 = d_sm[q * DS + col + 2];

            float l[32];
#pragma unroll
            for (int k = 0; k < 32; k++) {
                float a0 = __shfl_sync(0xffffffffu, sd0, k);
                float a1 = __shfl_sync(0xffffffffu, sd1, k);
                float a2 = __shfl_sync(0xffffffffu, sd2, k);
                l[k] = (sp0 * a0 + sp1 * a1 + sp2 * a2) * scale;
            }
            float m = l[0];
#pragma unroll
            for (int k = 1; k < 32; k++) m = fmaxf(m, l[k]);

            float ssum = 0.f, o0 = 0.f, o1 = 0.f, o2 = 0.f;
#pragma unroll
            for (int k = 0; k < 32; k++) {
                float e = __expf(l[k] - m);
                ssum += e;
                float a0 = __shfl_sync(0xffffffffu, sd0, k);
                float a1 = __shfl_sync(0xffffffffu, sd1, k);
                float a2 = __shfl_sync(0xffffffffu, sd2, k);
                o0 = fmaf(e, a0, o0);
                o1 = fmaf(e, a1, o1);
                o2 = fmaf(e, a2, o2);
            }
            const float inv = 1.0f / ssum;
            o0 *= inv; o1 *= inv; o2 *= inv;

            float y0 = o0 * wl[3 * q + 0] + o1 * wl[3 * q + 1] + o2 * wl[3 * q + 2];
            float y1 = o0 * wl[96 + 3 * q + 0] + o1 * wl[96 + 3 * q + 1] + o2 * wl[96 + 3 * q + 2];
#pragma unroll
            for (int off = 16; off > 0; off >>= 1) {
                y0 += __shfl_xor_sync(0xffffffffu, y0, off);
                y1 += __shfl_xor_sync(0xffffffffu, y1, off);
            }
            if (lane == 0) {
                const int bp = r + 1024 * n;
                out[2 * bp + 0] = y0 + b0;
                out[2 * bp + 1] = y1 + b1;
            }
        }
        __syncthreads();   // d_sm/p_sm reads done before next iter's conv writes
    }
}

extern "C" void kernel_launch(void* const* d_in, const int* in_sizes, int n_in,
                              void* d_out, int out_size)
{
    (void)in_sizes; (void)n_in; (void)out_size;
    const float* dna    = (const float*)d_in[0];
    const float* prot   = (const float*)d_in[1];
    const float* w_dna  = (const float*)d_in[2];
    const float* w_prot = (const float*)d_in[3];
    const float* w_lin  = (const float*)d_in[4];
    const float* b_lin  = (const float*)d_in[5];

    int nsm = 0;
    cudaDeviceGetAttribute(&nsm, cudaDevAttrMultiProcessorCount, 0);
    if (nsm < 1) nsm = 148;
    int grid = nsm;
    if (grid > NR) grid = NR;

    cudaFuncSetAttribute(fused_matx_v3,
                         cudaFuncAttributeMaxDynamicSharedMemorySize, SMEM_BYTES);
    fused_matx_v3<<<grid, 256, SMEM_BYTES>>>(dna, prot, w_dna, w_prot, w_lin, b_lin,
                                             (float*)d_out);
}

// round 7
// speedup vs baseline: 2.1302x; 1.0517x over previous
#include <cuda_runtime.h>
#include <cstdint>

typedef unsigned long long ull;

// Fused conv+relu (dna, prot) -> chunk shuffle -> 32x32x3 attention -> 96->2
// linear. v7 == v6 resubmission (R6 container failure was infra: the untouched
// stub also "failed twice" in R0; failures alternate rounds independent of
// kernel content).
//
// Design: persistent CTAs (grid=#SMs) + UBLKCP double-buffered staging,
// f32x2 channel-paired conv, single-pass packed attention (no max-subtract;
// logits bounded so fp32 exp is safe).
//
// Shuffle algebra: sd[b',q,c] = d[32*(b'&1023)+q, 3*(b'>>10)+c]  (B=2^15).

#define NR 1024
#define CLEN 103
#define RLEN_DNA 412
#define RLEN_PROT 2163
#define DS 97
#define PB_FLOATS (8 * RLEN_PROT)
#define DNA_FLOATS (32 * RLEN_DNA)
#define CH_BYTES (PB_FLOATS * 4)
#define DNA_BYTES (DNA_FLOATS * 4)

// smem layout (floats)
#define OFF_MBAR 0                   // 3 x u64 (16 floats reserved)
#define OFF_WD2  16                  // 2 ch-pairs x 8 ull = 32 floats
#define OFF_WP2  48                  // 10 ch-pairs x 8 ull = 160 floats
#define OFF_WPL  208                 // leftover prot channel: 8 floats
#define OFF_WL   216                 // 192
#define OFF_BL   408                 // 2
#define OFF_PB0  416                 // 16B aligned (416*4 = 1664)
#define OFF_PB1  (OFF_PB0 + PB_FLOATS)
#define OFF_DNA  (OFF_PB0 + 2 * PB_FLOATS)
#define OFF_DSM  (OFF_DNA + DNA_FLOATS)
#define OFF_PSM  (OFF_DSM + 32 * DS)
#define SMEM_FLOATS (OFF_PSM + 32 * DS)
#define SMEM_BYTES (SMEM_FLOATS * 4)

// ── packed f32x2 helpers (PTX ISA 8.6, sm_100a) ──
__device__ __forceinline__ ull pk(float lo, float hi) {
    ull r; asm("mov.b64 %0,{%1,%2};" : "=l"(r) : "f"(lo), "f"(hi)); return r;
}
__device__ __forceinline__ void upk(ull v, float& lo, float& hi) {
    asm("mov.b64 {%0,%1},%2;" : "=f"(lo), "=f"(hi) : "l"(v));
}
__device__ __forceinline__ ull fma2(ull a, ull b, ull c) {
    ull d; asm("fma.rn.f32x2 %0,%1,%2,%3;" : "=l"(d) : "l"(a), "l"(b), "l"(c)); return d;
}
__device__ __forceinline__ ull mul2(ull a, ull b) {
    ull d; asm("mul.rn.f32x2 %0,%1,%2;" : "=l"(d) : "l"(a), "l"(b)); return d;
}
__device__ __forceinline__ ull add2(ull a, ull b) {
    ull d; asm("add.rn.f32x2 %0,%1,%2;" : "=l"(d) : "l"(a), "l"(b)); return d;
}
__device__ __forceinline__ float ex2f(float x) {
    float y; asm("ex2.approx.f32 %0,%1;" : "=f"(y) : "f"(x)); return y;
}

// ── mbarrier / bulk-copy (forms proven in v3 pass) ──
__device__ __forceinline__ uint32_t s2u(const void* p) {
    uint32_t a;
    asm("{ .reg .u64 t; cvta.to.shared.u64 t, %1; cvt.u32.u64 %0, t; }"
        : "=r"(a) : "l"(p));
    return a;
}
__device__ __forceinline__ void mbar_init(uint32_t mbar, uint32_t cnt) {
    asm volatile("mbarrier.init.shared.b64 [%0], %1;" :: "r"(mbar), "r"(cnt) : "memory");
}
__device__ __forceinline__ void mbar_expect_tx(uint32_t mbar, uint32_t bytes) {
    asm volatile("mbarrier.arrive.expect_tx.shared.b64 _, [%0], %1;"
                 :: "r"(mbar), "r"(bytes) : "memory");
}
__device__ __forceinline__ void mbar_wait(uint32_t mbar, uint32_t parity) {
    uint32_t done;
    asm volatile(
        "{\n\t.reg .pred p;\n\t"
        "mbarrier.try_wait.parity.acquire.cta.shared::cta.b64 p, [%1], %2;\n\t"
        "selp.b32 %0, 1, 0, p;\n\t}"
        : "=r"(done) : "r"(mbar), "r"(parity) : "memory");
    if (!done) {
        asm volatile(
            "{\n\t.reg .pred P1;\n\t"
            "WL_%=:\n\t"
            "mbarrier.try_wait.parity.acquire.cta.shared::cta.b64 P1, [%0], %1, 0x989680;\n\t"
            "@P1 bra.uni WD_%=;\n\t"
            "bra.uni WL_%=;\n\t"
            "WD_%=:\n\t}"
            :: "r"(mbar), "r"(parity) : "memory");
    }
}
__device__ __forceinline__ void bulk_g2s(uint32_t dst, const void* src,
                                         uint32_t bytes, uint32_t mbar) {
    asm volatile(
        "cp.async.bulk.shared::cluster.global.mbarrier::complete_tx::bytes "
        "[%0], [%1], %2, [%3];"
        :: "r"(dst), "l"(src), "r"(bytes), "r"(mbar) : "memory");
}

// One warp computes one conv row; lane covers outputs 3*lane..3*lane+2.
// Channel-paired f32x2: .x accumulates even channels, .y odd channels.
template <int NCP, bool LEFT>
__device__ __forceinline__ void conv_row_cp(
    const float* __restrict__ xrow, const ull* __restrict__ w2,
    const float* __restrict__ wleft, float* __restrict__ orow, int lane)
{
    const int t = 3 * lane;
    float s0 = 0.f, s1 = 0.f, s2 = 0.f;
    if (LEFT) {   // leftover (odd channel count) channel, scalar
        const float* xb = xrow + 2 * NCP * CLEN + t;
        float x[10];
#pragma unroll
        for (int u = 0; u < 10; u++) x[u] = xb[u];
#pragma unroll
        for (int j = 0; j < 8; j++) {
            const float wv = wleft[j];
            s0 = fmaf(x[j],     wv, s0);
            s1 = fmaf(x[j + 1], wv, s1);
            s2 = fmaf(x[j + 2], wv, s2);
        }
    }
    ull a0 = pk(s0, 0.f), a1 = pk(s1, 0.f), a2 = pk(s2, 0.f);
#pragma unroll
    for (int cp = 0; cp < NCP; cp++) {
        const float* xe = xrow + (2 * cp) * CLEN + t;
        const float* xo = xe + CLEN;
        ull px[10];
#pragma unroll
        for (int u = 0; u < 10; u++) px[u] = pk(xe[u], xo[u]);
#pragma unroll
        for (int j = 0; j < 8; j++) {
            const ull w = w2[cp * 8 + j];
            a0 = fma2(px[j],     w, a0);
            a1 = fma2(px[j + 1], w, a1);
            a2 = fma2(px[j + 2], w, a2);
        }
    }
    float lo, hi;
    upk(a0, lo, hi); orow[t + 0] = fmaxf(lo + hi, 0.f);
    upk(a1, lo, hi); orow[t + 1] = fmaxf(lo + hi, 0.f);
    upk(a2, lo, hi); orow[t + 2] = fmaxf(lo + hi, 0.f);
}

__global__ __launch_bounds__(256)
void fused_matx_v7(const float* __restrict__ dna, const float* __restrict__ prot,
                   const float* __restrict__ w_dna, const float* __restrict__ w_prot,
                   const float* __restrict__ w_lin, const float* __restrict__ b_lin,
                   float* __restrict__ out)
{
    extern __shared__ float sm[];
    uint64_t* mbars = (uint64_t*)(sm + OFF_MBAR);
    ull* wd2 = (ull*)(sm + OFF_WD2);
    ull* wp2 = (ull*)(sm + OFF_WP2);
    float* wpl = sm + OFF_WPL;
    float* wl  = sm + OFF_WL;
    float* bl  = sm + OFF_BL;
    float* pb[2] = { sm + OFF_PB0, sm + OFF_PB1 };
    float* dna_st = sm + OFF_DNA;
    float* d_sm = sm + OFF_DSM;
    float* p_sm = sm + OFF_PSM;

    const int tid  = threadIdx.x;
    const int w    = tid >> 5;
    const int lane = tid & 31;
    const int bid  = blockIdx.x;
    const int grid = gridDim.x;

    const uint32_t mb_p[2] = { s2u(&mbars[0]), s2u(&mbars[1]) };
    const uint32_t mb_dna  = s2u(&mbars[2]);
    const uint32_t pbu[2]  = { s2u(pb[0]), s2u(pb[1]) };
    const uint32_t dnau    = s2u(dna_st);

    if (tid == 0) { mbar_init(mb_p[0], 1); mbar_init(mb_p[1], 1); mbar_init(mb_dna, 1); }
    // weight staging: disjoint arrays, independent guards (all < blockDim)
    if (tid < 80)  wp2[tid] = pk(w_prot[(tid >> 3) * 16 + (tid & 7)],
                                 w_prot[(tid >> 3) * 16 + 8 + (tid & 7)]);
    if (tid < 16)  wd2[tid] = pk(w_dna[(tid >> 3) * 16 + (tid & 7)],
                                 w_dna[(tid >> 3) * 16 + 8 + (tid & 7)]);
    if (tid < 8)   wpl[tid] = w_prot[160 + tid];
    if (tid < 192) wl[tid]  = w_lin[tid];
    if (tid < 2)   bl[tid]  = b_lin[tid];
    __syncthreads();

    // prologue copies: dna(r0), prot chunks 0,1
    if (tid == 0) {
        mbar_expect_tx(mb_dna, DNA_BYTES);
        bulk_g2s(dnau, dna + (size_t)bid * DNA_FLOATS, DNA_BYTES, mb_dna);
        mbar_expect_tx(mb_p[0], CH_BYTES);
        bulk_g2s(pbu[0], prot + (size_t)(32 * bid) * RLEN_PROT, CH_BYTES, mb_p[0]);
        mbar_expect_tx(mb_p[1], CH_BYTES);
        bulk_g2s(pbu[1], prot + (size_t)(32 * bid + 8) * RLEN_PROT, CH_BYTES, mb_p[1]);
    }

    const float b0 = bl[0], b1 = bl[1];
    const float SCL = 0.5773502691896258f * 1.4426950408889634f;  // scale*log2e

    int it = 0;
    for (int r = bid; r < NR; r += grid, it++) {
        // ── dna conv: warp w does rows w, w+8, w+16, w+24 ──
        mbar_wait(mb_dna, it & 1);
#pragma unroll
        for (int i = 0; i < 4; i++) {
            const int row = w + 8 * i;
            conv_row_cp<2, false>(dna_st + row * RLEN_DNA, wd2, nullptr,
                                  d_sm + row * DS, lane);
        }
        __syncthreads();                     // dna_st free
        if (tid == 0 && r + grid < NR) {     // prefetch next r's dna
            mbar_expect_tx(mb_dna, DNA_BYTES);
            bulk_g2s(dnau, dna + (size_t)(r + grid) * DNA_FLOATS, DNA_BYTES, mb_dna);
        }

        // ── prot conv: global chunk stream s = 4*it + j ──
#pragma unroll
        for (int j = 0; j < 4; j++) {
            const int s = 4 * it + j;
            const int b = s & 1;
            mbar_wait(mb_p[b], (s >> 1) & 1);
            conv_row_cp<10, true>(pb[b] + w * RLEN_PROT, wp2, wpl,
                                  p_sm + (8 * j + w) * DS, lane);
            __syncthreads();                 // buffer b free
            const int s2i = s + 2;
            const int r2 = bid + (s2i >> 2) * grid;
            if (tid == 0 && r2 < NR) {
                mbar_expect_tx(mb_p[s2i & 1], CH_BYTES);
                bulk_g2s(pbu[s2i & 1],
                         prot + (size_t)(32 * r2 + 8 * (s2i & 3)) * RLEN_PROT,
                         CH_BYTES, mb_p[s2i & 1]);
            }
        }

        // ── attention + linear (single pass, packed k-pairs) ──
        const int q = lane;
#pragma unroll
        for (int itc = 0; itc < 4; itc++) {
            const int n = w + 8 * itc;
            const int col = 3 * n;

            const float sp0 = p_sm[q * DS + col + 0] * SCL;
            const float sp1 = p_sm[q * DS + col + 1] * SCL;
            const float sp2 = p_sm[q * DS + col + 2] * SCL;
            const float sd0 = d_sm[q * DS + col + 0];
            const float sd1 = d_sm[q * DS + col + 1];
            const float sd2 = d_sm[q * DS + col + 2];

            const ull sp0p = pk(sp0, sp0);
            const ull sp1p = pk(sp1, sp1);
            const ull sp2p = pk(sp2, sp2);

            ull ssum2 = pk(0.f, 0.f);
            ull o0p = ssum2, o1p = ssum2, o2p = ssum2;
#pragma unroll
            for (int k = 0; k < 32; k += 2) {
                const float b00 = __shfl_sync(0xffffffffu, sd0, k);
                const float b01 = __shfl_sync(0xffffffffu, sd0, k + 1);
                const float b10 = __shfl_sync(0xffffffffu, sd1, k);
                const float b11 = __shfl_sync(0xffffffffu, sd1, k + 1);
                const float b20 = __shfl_sync(0xffffffffu, sd2, k);
                const float b21 = __shfl_sync(0xffffffffu, sd2, k + 1);
                const ull a0p = pk(b00, b01);
                const ull a1p = pk(b10, b11);
                const ull a2p = pk(b20, b21);
                const ull lp = fma2(sp2p, a2p, fma2(sp1p, a1p, mul2(sp0p, a0p)));
                float l0, l1; upk(lp, l0, l1);
                const ull ep = pk(ex2f(l0), ex2f(l1));
                ssum2 = add2(ssum2, ep);
                o0p = fma2(ep, a0p, o0p);
                o1p = fma2(ep, a1p, o1p);
                o2p = fma2(ep, a2p, o2p);
            }
            float sa, sb; upk(ssum2, sa, sb);
            const float inv = __fdividef(1.f, sa + sb);
            float xa, xb;
            upk(o0p, xa, xb); const float o0 = (xa + xb) * inv;
            upk(o1p, xa, xb); const float o1 = (xa + xb) * inv;
            upk(o2p, xa, xb); const float o2 = (xa + xb) * inv;

            float y0 = o0 * wl[3 * q + 0] + o1 * wl[3 * q + 1] + o2 * wl[3 * q + 2];
            float y1 = o0 * wl[96 + 3 * q + 0] + o1 * wl[96 + 3 * q + 1] + o2 * wl[96 + 3 * q + 2];
#pragma unroll
            for (int off = 16; off > 0; off >>= 1) {
                y0 += __shfl_xor_sync(0xffffffffu, y0, off);
                y1 += __shfl_xor_sync(0xffffffffu, y1, off);
            }
            if (lane == 0) {
                const int bp = r + 1024 * n;
                *(float2*)(out + 2 * bp) = make_float2(y0 + b0, y1 + b1);
            }
        }
        __syncthreads();   // d_sm/p_sm reads done before next iter's conv writes
    }
}

extern "C" void kernel_launch(void* const* d_in, const int* in_sizes, int n_in,
                              void* d_out, int out_size)
{
    (void)in_sizes; (void)n_in; (void)out_size;
    const float* dna    = (const float*)d_in[0];
    const float* prot   = (const float*)d_in[1];
    const float* w_dna  = (const float*)d_in[2];
    const float* w_prot = (const float*)d_in[3];
    const float* w_lin  = (const float*)d_in[4];
    const float* b_lin  = (const float*)d_in[5];

    int nsm = 0;
    if (cudaDeviceGetAttribute(&nsm, cudaDevAttrMultiProcessorCount, 0) != cudaSuccess
        || nsm < 1) nsm = 148;
    int grid = nsm;
    if (grid > NR) grid = NR;

    cudaFuncSetAttribute(fused_matx_v7,
                         cudaFuncAttributeMaxDynamicSharedMemorySize, SMEM_BYTES);
    fused_matx_v7<<<grid, 256, SMEM_BYTES>>>(dna, prot, w_dna, w_prot, w_lin, b_lin,
                                             (float*)d_out);
}

// round 11
// speedup vs baseline: 2.3610x; 1.1083x over previous
#include <cuda_runtime.h>
#include <cstdint>

typedef unsigned long long ull;

// Fused conv+relu (dna, prot) -> chunk shuffle -> 32x32x3 attention -> 96->2
// linear. v11 = proven v7 pipeline (persistent CTAs, UBLKCP double-buffered
// 8-row prot chunks, tid0-issued copies, CTA-barrier protection) with the prot
// conv remapped to channel-split 6-outputs-per-lane (13-float window, lane
// pairs split even/odd channels, combine via shfl_xor) to cut LDS ~35%.
//
// Shuffle algebra: sd[b',q,c] = d[32*(b'&1023)+q, 3*(b'>>10)+c]  (B=2^15).

#define NR 1024
#define CLEN 103
#define RLEN_DNA 412
#define RLEN_PROT 2163
#define DS 97
#define PB_FLOATS (8 * RLEN_PROT)            // 17304 per buffer (8 rows)
#define DNA_FLOATS (32 * RLEN_DNA)           // 13184
#define CH_BYTES (PB_FLOATS * 4)             // 69216
#define DNA_BYTES (DNA_FLOATS * 4)           // 52736

// smem layout (floats)
#define OFF_MBAR 0                   // 3 x u64 (16 floats reserved)
#define OFF_WD2  16                  // 16 ull = 32 floats (dna ch-pairs)
#define OFF_WQ2  48                  // 80 ull = 160 floats (prot same-parity ch-pairs)
#define OFF_WPL  208                 // 8 (prot channel 20, scalar)
#define OFF_WL   216                 // 192
#define OFF_BL   408                 // 2
#define OFF_PB0  416                 // 16B aligned (416*4 = 1664)
#define OFF_PB1  (OFF_PB0 + PB_FLOATS)
#define OFF_DNA  (OFF_PB0 + 2 * PB_FLOATS)
#define OFF_DSM  (OFF_DNA + DNA_FLOATS)
#define OFF_PSM  (OFF_DSM + 32 * DS)
#define SMEM_FLOATS (OFF_PSM + 32 * DS)
#define SMEM_BYTES (SMEM_FLOATS * 4)         // 217664

// ── packed f32x2 helpers ──
__device__ __forceinline__ ull pk(float lo, float hi) {
    ull r; asm("mov.b64 %0,{%1,%2};" : "=l"(r) : "f"(lo), "f"(hi)); return r;
}
__device__ __forceinline__ void upk(ull v, float& lo, float& hi) {
    asm("mov.b64 {%0,%1},%2;" : "=f"(lo), "=f"(hi) : "l"(v));
}
__device__ __forceinline__ ull fma2(ull a, ull b, ull c) {
    ull d; asm("fma.rn.f32x2 %0,%1,%2,%3;" : "=l"(d) : "l"(a), "l"(b), "l"(c)); return d;
}
__device__ __forceinline__ ull mul2(ull a, ull b) {
    ull d; asm("mul.rn.f32x2 %0,%1,%2;" : "=l"(d) : "l"(a), "l"(b)); return d;
}
__device__ __forceinline__ ull add2(ull a, ull b) {
    ull d; asm("add.rn.f32x2 %0,%1,%2;" : "=l"(d) : "l"(a), "l"(b)); return d;
}
__device__ __forceinline__ float ex2f(float x) {
    float y; asm("ex2.approx.f32 %0,%1;" : "=f"(y) : "f"(x)); return y;
}

// ── mbarrier / bulk-copy (proven v3/v7 forms) ──
__device__ __forceinline__ uint32_t s2u(const void* p) {
    uint32_t a;
    asm("{ .reg .u64 t; cvta.to.shared.u64 t, %1; cvt.u32.u64 %0, t; }"
        : "=r"(a) : "l"(p));
    return a;
}
__device__ __forceinline__ void mbar_init(uint32_t mbar, uint32_t cnt) {
    asm volatile("mbarrier.init.shared.b64 [%0], %1;" :: "r"(mbar), "r"(cnt) : "memory");
}
__device__ __forceinline__ void mbar_expect_tx(uint32_t mbar, uint32_t bytes) {
    asm volatile("mbarrier.arrive.expect_tx.shared.b64 _, [%0], %1;"
                 :: "r"(mbar), "r"(bytes) : "memory");
}
__device__ __forceinline__ void mbar_wait(uint32_t mbar, uint32_t parity) {
    uint32_t done;
    asm volatile(
        "{\n\t.reg .pred p;\n\t"
        "mbarrier.try_wait.parity.acquire.cta.shared::cta.b64 p, [%1], %2;\n\t"
        "selp.b32 %0, 1, 0, p;\n\t}"
        : "=r"(done) : "r"(mbar), "r"(parity) : "memory");
    if (!done) {
        asm volatile(
            "{\n\t.reg .pred P1;\n\t"
            "WL_%=:\n\t"
            "mbarrier.try_wait.parity.acquire.cta.shared::cta.b64 P1, [%0], %1, 0x989680;\n\t"
            "@P1 bra.uni WD_%=;\n\t"
            "bra.uni WL_%=;\n\t"
            "WD_%=:\n\t}"
            :: "r"(mbar), "r"(parity) : "memory");
    }
}
__device__ __forceinline__ void bulk_g2s(uint32_t dst, const void* src,
                                         uint32_t bytes, uint32_t mbar) {
    asm volatile(
        "cp.async.bulk.shared::cluster.global.mbarrier::complete_tx::bytes "
        "[%0], [%1], %2, [%3];"
        :: "r"(dst), "l"(src), "r"(bytes), "r"(mbar) : "memory");
}

// dna conv: lane covers outputs 3*lane..3*lane+2 (proven v7 form).
__device__ __forceinline__ void conv_row_dna(
    const float* __restrict__ xrow, const ull* __restrict__ w2,
    float* __restrict__ orow, int lane)
{
    const int t = 3 * lane;
    ull a0 = pk(0.f, 0.f), a1 = a0, a2 = a0;
#pragma unroll
    for (int cp = 0; cp < 2; cp++) {
        const float* xe = xrow + (2 * cp) * CLEN + t;
        const float* xo = xe + CLEN;
        ull px[10];
#pragma unroll
        for (int u = 0; u < 10; u++) px[u] = pk(xe[u], xo[u]);
#pragma unroll
        for (int j = 0; j < 8; j++) {
            const ull w = w2[cp * 8 + j];
            a0 = fma2(px[j],     w, a0);
            a1 = fma2(px[j + 1], w, a1);
            a2 = fma2(px[j + 2], w, a2);
        }
    }
    float lo, hi;
    upk(a0, lo, hi); orow[t + 0] = fmaxf(lo + hi, 0.f);
    upk(a1, lo, hi); orow[t + 1] = fmaxf(lo + hi, 0.f);
    upk(a2, lo, hi); orow[t + 2] = fmaxf(lo + hi, 0.f);
}

// prot conv, channel-split 6-outputs-per-lane. One warp per row.
// Lane: B = lane>>1 (outputs [6B, 6B+6)), H = lane&1 (channel parity).
// Lane covers channels {H, H+2, ..., H+18} as 5 f32x2 pairs (c, c+2);
// even lanes also do scalar channel 20. Partner lanes combine via shfl_xor(1).
// Bank-conflict-free: even-lane residues (6B+even const) are 16 distinct evens,
// odd-lane +103 == +7 (mod 32) gives 16 distinct odds.
__device__ __forceinline__ void conv_row6_prot(
    const float* __restrict__ xrow,     // buffer + row*RLEN_PROT
    const ull* __restrict__ wq2, const float* __restrict__ wpl,
    float* __restrict__ orow,           // p_sm + row*DS
    int lane)
{
    const int B = lane >> 1;
    const int H = lane & 1;
    const int t = 6 * B;

    ull acc[6];
#pragma unroll
    for (int o = 0; o < 6; o++) acc[o] = pk(0.f, 0.f);

#pragma unroll
    for (int p = 0; p < 5; p++) {
        const float* xa = xrow + (H + 4 * p) * CLEN + t;
        const float* xb = xa + 2 * CLEN;
        ull px[13];
#pragma unroll
        for (int u = 0; u < 13; u++) px[u] = pk(xa[u], xb[u]);
        const ull* wj = wq2 + (H * 5 + p) * 8;
#pragma unroll
        for (int o = 0; o < 6; o++) {
#pragma unroll
            for (int j = 0; j < 8; j++) acc[o] = fma2(px[o + j], wj[j], acc[o]);
        }
    }

    float part[6];
    float lo, hi;
#pragma unroll
    for (int o = 0; o < 6; o++) { upk(acc[o], lo, hi); part[o] = lo + hi; }

    if (H == 0) {   // scalar channel 20 (even lanes only)
        const float* xc = xrow + 20 * CLEN + t;
        float x[13];
#pragma unroll
        for (int u = 0; u < 13; u++) x[u] = xc[u];
#pragma unroll
        for (int o = 0; o < 6; o++) {
#pragma unroll
            for (int j = 0; j < 8; j++) part[o] = fmaf(x[o + j], wpl[j], part[o]);
        }
    }

    // combine partner halves; even lane stores outputs 0-2, odd 3-5
    float full[6];
#pragma unroll
    for (int o = 0; o < 6; o++)
        full[o] = part[o] + __shfl_xor_sync(0xffffffffu, part[o], 1);

    if (H == 0) {
        orow[t + 0] = fmaxf(full[0], 0.f);
        orow[t + 1] = fmaxf(full[1], 0.f);
        orow[t + 2] = fmaxf(full[2], 0.f);
    } else {
        orow[t + 3] = fmaxf(full[3], 0.f);
        orow[t + 4] = fmaxf(full[4], 0.f);
        orow[t + 5] = fmaxf(full[5], 0.f);
    }
}

__global__ __launch_bounds__(256)
void fused_matx_v11(const float* __restrict__ dna, const float* __restrict__ prot,
                    const float* __restrict__ w_dna, const float* __restrict__ w_prot,
                    const float* __restrict__ w_lin, const float* __restrict__ b_lin,
                    float* __restrict__ out)
{
    extern __shared__ float sm[];
    uint64_t* mbars = (uint64_t*)(sm + OFF_MBAR);   // [0]=p0 [1]=p1 [2]=dna
    ull* wd2 = (ull*)(sm + OFF_WD2);
    ull* wq2 = (ull*)(sm + OFF_WQ2);
    float* wpl = sm + OFF_WPL;
    float* wl  = sm + OFF_WL;
    float* bl  = sm + OFF_BL;
    float* pb[2] = { sm + OFF_PB0, sm + OFF_PB1 };
    float* dna_st = sm + OFF_DNA;
    float* d_sm = sm + OFF_DSM;
    float* p_sm = sm + OFF_PSM;

    const int tid  = threadIdx.x;
    const int w    = tid >> 5;
    const int lane = tid & 31;
    const int bid  = blockIdx.x;
    const int grid = gridDim.x;

    const uint32_t mb_p[2] = { s2u(&mbars[0]), s2u(&mbars[1]) };
    const uint32_t mb_dna  = s2u(&mbars[2]);
    const uint32_t pbu[2]  = { s2u(pb[0]), s2u(pb[1]) };
    const uint32_t dnau    = s2u(dna_st);

    if (tid == 0) { mbar_init(mb_p[0], 1); mbar_init(mb_p[1], 1); mbar_init(mb_dna, 1); }
    // prot same-parity channel pairs: pair_id=tid>>3 (H=pair_id/5, p=pair_id%5),
    // j=tid&7; channels (c1, c1+2) with c1 = H + 4p.
    if (tid < 80) {
        const int pair_id = tid >> 3, j = tid & 7;
        const int H = pair_id / 5, p = pair_id % 5;
        const int c1 = H + 4 * p;
        wq2[tid] = pk(w_prot[c1 * 8 + j], w_prot[(c1 + 2) * 8 + j]);
    }
    if (tid < 16)  wd2[tid] = pk(w_dna[(tid >> 3) * 16 + (tid & 7)],
                                 w_dna[(tid >> 3) * 16 + 8 + (tid & 7)]);
    if (tid < 8)   wpl[tid] = w_prot[160 + tid];
    if (tid < 192) wl[tid]  = w_lin[tid];
    if (tid < 2)   bl[tid]  = b_lin[tid];
    __syncthreads();

    // prologue copies: dna(r0), prot chunks 0,1
    if (tid == 0) {
        mbar_expect_tx(mb_dna, DNA_BYTES);
        bulk_g2s(dnau, dna + (size_t)bid * DNA_FLOATS, DNA_BYTES, mb_dna);
        mbar_expect_tx(mb_p[0], CH_BYTES);
        bulk_g2s(pbu[0], prot + (size_t)(32 * bid) * RLEN_PROT, CH_BYTES, mb_p[0]);
        mbar_expect_tx(mb_p[1], CH_BYTES);
        bulk_g2s(pbu[1], prot + (size_t)(32 * bid + 8) * RLEN_PROT, CH_BYTES, mb_p[1]);
    }

    const float b0 = bl[0], b1 = bl[1];
    const float SCL = 0.5773502691896258f * 1.4426950408889634f;  // scale*log2e

    int it = 0;
    for (int r = bid; r < NR; r += grid, it++) {
        // ── dna conv: warp w does rows w, w+8, w+16, w+24 ──
        mbar_wait(mb_dna, it & 1);
#pragma unroll
        for (int i = 0; i < 4; i++) {
            const int row = w + 8 * i;
            conv_row_dna(dna_st + row * RLEN_DNA, wd2, d_sm + row * DS, lane);
        }
        __syncthreads();                     // dna_st free
        if (tid == 0 && r + grid < NR) {     // prefetch next r's dna
            mbar_expect_tx(mb_dna, DNA_BYTES);
            bulk_g2s(dnau, dna + (size_t)(r + grid) * DNA_FLOATS, DNA_BYTES, mb_dna);
        }

        // ── prot conv: chunk stream s = 4*it + j; warp w does row 8j+w ──
#pragma unroll
        for (int j = 0; j < 4; j++) {
            const int s = 4 * it + j;
            const int b = s & 1;
            mbar_wait(mb_p[b], (s >> 1) & 1);
            conv_row6_prot(pb[b] + w * RLEN_PROT, wq2, wpl,
                           p_sm + (8 * j + w) * DS, lane);
            __syncthreads();                 // buffer b free
            const int s2i = s + 2;
            const int r2 = bid + (s2i >> 2) * grid;
            if (tid == 0 && r2 < NR) {
                mbar_expect_tx(mb_p[s2i & 1], CH_BYTES);
                bulk_g2s(pbu[s2i & 1],
                         prot + (size_t)(32 * r2 + 8 * (s2i & 3)) * RLEN_PROT,
                         CH_BYTES, mb_p[s2i & 1]);
            }
        }

        // ── attention + linear (single pass, packed k-pairs) ──
        const int q = lane;
#pragma unroll
        for (int itc = 0; itc < 4; itc++) {
            const int n = w + 8 * itc;
            const int col = 3 * n;

            const float sp0 = p_sm[q * DS + col + 0] * SCL;
            const float sp1 = p_sm[q * DS + col + 1] * SCL;
            const float sp2 = p_sm[q * DS + col + 2] * SCL;
            const float sd0 = d_sm[q * DS + col + 0];
            const float sd1 = d_sm[q * DS + col + 1];
            const float sd2 = d_sm[q * DS + col + 2];

            const ull sp0p = pk(sp0, sp0);
            const ull sp1p = pk(sp1, sp1);
            const ull sp2p = pk(sp2, sp2);

            ull ssum2 = pk(0.f, 0.f);
            ull o0p = ssum2, o1p = ssum2, o2p = ssum2;
#pragma unroll
            for (int k = 0; k < 32; k += 2) {
                const float b00 = __shfl_sync(0xffffffffu, sd0, k);
                const float b01 = __shfl_sync(0xffffffffu, sd0, k + 1);
                const float b10 = __shfl_sync(0xffffffffu, sd1, k);
                const float b11 = __shfl_sync(0xffffffffu, sd1, k + 1);
                const float b20 = __shfl_sync(0xffffffffu, sd2, k);
                const float b21 = __shfl_sync(0xffffffffu, sd2, k + 1);
                const ull a0p = pk(b00, b01);
                const ull a1p = pk(b10, b11);
                const ull a2p = pk(b20, b21);
                const ull lp = fma2(sp2p, a2p, fma2(sp1p, a1p, mul2(sp0p, a0p)));
                float l0, l1; upk(lp, l0, l1);
                const ull ep = pk(ex2f(l0), ex2f(l1));
                ssum2 = add2(ssum2, ep);
                o0p = fma2(ep, a0p, o0p);
                o1p = fma2(ep, a1p, o1p);
                o2p = fma2(ep, a2p, o2p);
            }
            float sa, sb; upk(ssum2, sa, sb);
            const float inv = __fdividef(1.f, sa + sb);
            float xa, xb;
            upk(o0p, xa, xb); const float o0 = (xa + xb) * inv;
            upk(o1p, xa, xb); const float o1 = (xa + xb) * inv;
            upk(o2p, xa, xb); const float o2 = (xa + xb) * inv;

            float y0 = o0 * wl[3 * q + 0] + o1 * wl[3 * q + 1] + o2 * wl[3 * q + 2];
            float y1 = o0 * wl[96 + 3 * q + 0] + o1 * wl[96 + 3 * q + 1] + o2 * wl[96 + 3 * q + 2];
#pragma unroll
            for (int off = 16; off > 0; off >>= 1) {
                y0 += __shfl_xor_sync(0xffffffffu, y0, off);
                y1 += __shfl_xor_sync(0xffffffffu, y1, off);
            }
            if (lane == 0) {
                const int bp = r + 1024 * n;
                *(float2*)(out + 2 * bp) = make_float2(y0 + b0, y1 + b1);
            }
        }
        __syncthreads();   // d_sm/p_sm reads done before next iter's conv writes
    }
}

extern "C" void kernel_launch(void* const* d_in, const int* in_sizes, int n_in,
                              void* d_out, int out_size)
{
    (void)in_sizes; (void)n_in; (void)out_size;
    const float* dna    = (const float*)d_in[0];
    const float* prot   = (const float*)d_in[1];
    const float* w_dna  = (const float*)d_in[2];
    const float* w_prot = (const float*)d_in[3];
    const float* w_lin  = (const float*)d_in[4];
    const float* b_lin  = (const float*)d_in[5];

    int nsm = 0;
    if (cudaDeviceGetAttribute(&nsm, cudaDevAttrMultiProcessorCount, 0) != cudaSuccess
        || nsm < 1) nsm = 148;
    int grid = nsm;
    if (grid > NR) grid = NR;

    cudaFuncSetAttribute(fused_matx_v11,
                         cudaFuncAttributeMaxDynamicSharedMemorySize, SMEM_BYTES);
    fused_matx_v11<<<grid, 256, SMEM_BYTES>>>(dna, prot, w_dna, w_prot, w_lin, b_lin,
                                              (float*)d_out);
}